// round 3
// baseline (speedup 1.0000x reference)
#include <cuda_runtime.h>

// Contour_to_mask via winding angles.
// angle_k = acos(clip(dot/(|d||r|), ±(1-1e-5))) == clamp(atan2(|cr|,dot), A0, pi-A0)
// sign_k = tanh(K*cr);  out = min(|sum_k sign_k*angle_k|/2pi, 1)
// 4 pixels per thread (same row, adjacent cols), y-math packed f32x2, x shared.

#define MSIZE   256
#define KV      64
#define NCONT   8
#define KCONST  100000.0f

typedef unsigned long long ull;

__device__ __forceinline__ ull pk(float lo, float hi) {
    ull r; asm("mov.b64 %0, {%1,%2};" : "=l"(r) : "f"(lo), "f"(hi)); return r;
}
__device__ __forceinline__ void upk(float& lo, float& hi, ull v) {
    asm("mov.b64 {%0,%1}, %2;" : "=f"(lo), "=f"(hi) : "l"(v));
}
__device__ __forceinline__ ull f2add(ull a, ull b) {
    ull d; asm("add.rn.f32x2 %0,%1,%2;" : "=l"(d) : "l"(a), "l"(b)); return d;
}
__device__ __forceinline__ ull f2mul(ull a, ull b) {
    ull d; asm("mul.rn.f32x2 %0,%1,%2;" : "=l"(d) : "l"(a), "l"(b)); return d;
}
__device__ __forceinline__ ull f2fma(ull a, ull b, ull c) {
    ull d; asm("fma.rn.f32x2 %0,%1,%2,%3;" : "=l"(d) : "l"(a), "l"(b), "l"(c)); return d;
}
__device__ __forceinline__ float frcp(float x) {
    float r; asm("rcp.approx.f32 %0,%1;" : "=f"(r) : "f"(x)); return r;
}
__device__ __forceinline__ float ftanh(float x) {
    float r; asm("tanh.approx.f32 %0,%1;" : "=f"(r) : "f"(x)); return r;
}

// atan minimax on [0,1]: atan(a) ~= a*(c0 + c1 s + ... + c5 s^5), s=a*a
#define AT_C0  0.99997726f
#define AT_C1 -0.33262347f
#define AT_C2  0.19354346f
#define AT_C3 -0.11643287f
#define AT_C4  0.05265332f
#define AT_C5 -0.01172120f

#define HPI     1.5707963267948966f
#define UMAX    1.5663241850f          /* pi/2 - acos(1-1e-5) */
#define INV2PI  0.15915494309189535f

__global__ void __launch_bounds__(256) contour_mask_kernel(
    const float* __restrict__ contour,   // [NCONT, KV, 2]
    float* __restrict__ out)             // [NCONT, MSIZE, MSIZE]
{
    __shared__ float sx[KV];
    __shared__ ull   sy2[KV];   // (cy, cy) broadcast pairs

    const int c = blockIdx.y;
    const float* cc = contour + c * (KV * 2);
    const int t = threadIdx.x;

    if (t < KV) {
        sx[t] = cc[2 * t];
        const float cy = cc[2 * t + 1];
        sy2[t] = pk(cy, cy);
    }
    __syncthreads();

    const int gid  = blockIdx.x * blockDim.x + t;     // 0 .. 16383
    const int pix0 = gid * 4;
    const float x  = (float)(pix0 >> 8)  * (1.0f / MSIZE);
    const float yb = (float)(pix0 & 255) * (1.0f / MSIZE);

    const ull negy01 = pk(-yb, -(yb + 1.0f / MSIZE));
    const ull negy23 = pk(-(yb + 2.0f / MSIZE), -(yb + 3.0f / MSIZE));

    const ull C0 = pk(AT_C0, AT_C0), C1 = pk(AT_C1, AT_C1), C2 = pk(AT_C2, AT_C2);
    const ull C3 = pk(AT_C3, AT_C3), C4 = pk(AT_C4, AT_C4), C5 = pk(AT_C5, AT_C5);
    const ull NM1 = pk(-1.0f, -1.0f);
    const ull HP2 = pk(HPI, HPI);
    const ull KP  = pk(KCONST, KCONST);

    float sum0 = 0.0f, sum1 = 0.0f, sum2 = 0.0f, sum3 = 0.0f;

    // k = 0 state
    float dx   = sx[0] - x;
    ull   dy01 = f2add(sy2[0], negy01);
    ull   dy23 = f2add(sy2[0], negy23);
    ull   NDX2 = pk(-dx, -dx);

#pragma unroll 8
    for (int k = 0; k < KV; k++) {
        const int kn = (k + 1) & (KV - 1);
        const float rx = sx[kn] - x;
        const ull ry01 = f2add(sy2[kn], negy01);
        const ull ry23 = f2add(sy2[kn], negy23);

        const float drs = dx * rx;
        const ull DRS2 = pk(drs, drs);
        const ull RX2  = pk(rx, rx);

        const ull dot01 = f2fma(dy01, ry01, DRS2);
        const ull dot23 = f2fma(dy23, ry23, DRS2);
        const ull cr01  = f2fma(dy01, RX2, f2mul(NDX2, ry01));
        const ull cr23  = f2fma(dy23, RX2, f2mul(NDX2, ry23));

        const ull q01 = f2mul(KP, cr01);
        const ull q23 = f2mul(KP, cr23);

        float crv[4], dv[4], qv[4];
        upk(crv[0], crv[1], cr01); upk(crv[2], crv[3], cr23);
        upk(dv[0],  dv[1],  dot01); upk(dv[2],  dv[3],  dot23);
        upk(qv[0],  qv[1],  q01);  upk(qv[2],  qv[3],  q23);

        float av[4], Af[4], Df[4];
#pragma unroll
        for (int j = 0; j < 4; j++) {
            Af[j] = fabsf(crv[j]);
            Df[j] = fabsf(dv[j]);
            const float mn = fminf(Af[j], Df[j]);
            const float mx = fmaxf(Af[j], Df[j]);
            av[j] = mn * frcp(mx);
        }

        const ull a01 = pk(av[0], av[1]);
        const ull a23 = pk(av[2], av[3]);
        const ull s01 = f2mul(a01, a01);
        const ull s23 = f2mul(a23, a23);

        ull p01 = f2fma(s01, C5, C4);
        ull p23 = f2fma(s23, C5, C4);
        p01 = f2fma(p01, s01, C3);  p23 = f2fma(p23, s23, C3);
        p01 = f2fma(p01, s01, C2);  p23 = f2fma(p23, s23, C2);
        p01 = f2fma(p01, s01, C1);  p23 = f2fma(p23, s23, C1);
        p01 = f2fma(p01, s01, C0);  p23 = f2fma(p23, s23, C0);
        const ull at01 = f2mul(p01, a01);
        const ull at23 = f2mul(p23, a23);
        const ull tp01 = f2fma(at01, NM1, HP2);   // pi/2 - atan
        const ull tp23 = f2fma(at23, NM1, HP2);

        float atv[4], tpv[4];
        upk(atv[0], atv[1], at01); upk(atv[2], atv[3], at23);
        upk(tpv[0], tpv[1], tp01); upk(tpv[2], tpv[3], tp23);

        float term[4];
#pragma unroll
        for (int j = 0; j < 4; j++) {
            float u = (Af[j] > Df[j]) ? atv[j] : tpv[j];
            u = fminf(u, UMAX);
            const float cs = __int_as_float(__float_as_int(u) |
                                            (__float_as_int(dv[j]) & 0x80000000u));
            const float angn = cs - HPI;          // -(angle)
            term[j] = ftanh(qv[j]) * angn;        // accumulate negated sum
        }
        sum0 += term[0]; sum1 += term[1]; sum2 += term[2]; sum3 += term[3];

        // rotate state
        dx = rx;
        dy01 = ry01;
        dy23 = ry23;
        NDX2 = pk(-rx, -rx);
    }

    float4 o;
    o.x = fminf(fabsf(sum0) * INV2PI, 1.0f);
    o.y = fminf(fabsf(sum1) * INV2PI, 1.0f);
    o.z = fminf(fabsf(sum2) * INV2PI, 1.0f);
    o.w = fminf(fabsf(sum3) * INV2PI, 1.0f);
    ((float4*)out)[c * (MSIZE * MSIZE / 4) + gid] = o;
}

extern "C" void kernel_launch(void* const* d_in, const int* in_sizes, int n_in,
                              void* d_out, int out_size)
{
    const float* contour = (const float*)d_in[0];
    float* out = (float*)d_out;

    dim3 grid((MSIZE * MSIZE) / (4 * 256), NCONT);   // 64 x 8 = 512 blocks
    contour_mask_kernel<<<grid, 256>>>(contour, out);
}

// round 4
// speedup vs baseline: 1.0545x; 1.0545x over previous
#include <cuda_runtime.h>

// Contour_to_mask via winding angles.
// angle_k = acos(clip(dot/(|d||r|), ±(1-1e-5))) == clamp(atan2(|cr|,dot), A0, pi-A0)
// sign_k = tanh(K*cr);  out = min(|sum_k sign_k*angle_k|/2pi, 1)
//
// 64-thread blocks, 2 pixels/thread (same row), 2 tiles of 128 px per block.
// Scalar per-pixel math; only the atan polynomial is packed f32x2.

#define MSIZE   256
#define KV      64
#define NCONT   8
#define KCONST  100000.0f

typedef unsigned long long ull;

__device__ __forceinline__ ull pk(float lo, float hi) {
    ull r; asm("mov.b64 %0, {%1,%2};" : "=l"(r) : "f"(lo), "f"(hi)); return r;
}
__device__ __forceinline__ void upk(float& lo, float& hi, ull v) {
    asm("mov.b64 {%0,%1}, %2;" : "=f"(lo), "=f"(hi) : "l"(v));
}
__device__ __forceinline__ ull f2mul(ull a, ull b) {
    ull d; asm("mul.rn.f32x2 %0,%1,%2;" : "=l"(d) : "l"(a), "l"(b)); return d;
}
__device__ __forceinline__ ull f2fma(ull a, ull b, ull c) {
    ull d; asm("fma.rn.f32x2 %0,%1,%2,%3;" : "=l"(d) : "l"(a), "l"(b), "l"(c)); return d;
}
__device__ __forceinline__ float frcp(float x) {
    float r; asm("rcp.approx.f32 %0,%1;" : "=f"(r) : "f"(x)); return r;
}
__device__ __forceinline__ float ftanh(float x) {
    float r; asm("tanh.approx.f32 %0,%1;" : "=f"(r) : "f"(x)); return r;
}

// atan minimax on [0,1]: atan(a) ~= a*(c0 + c1 s + ... + c5 s^5), s=a*a
#define AT_C0  0.99997726f
#define AT_C1 -0.33262347f
#define AT_C2  0.19354346f
#define AT_C3 -0.11643287f
#define AT_C4  0.05265332f
#define AT_C5 -0.01172120f

#define HPI     1.5707963267948966f
#define UMAX    1.5663241850f          /* pi/2 - acos(1-1e-5) */
#define INV2PI  0.15915494309189535f

__global__ void __launch_bounds__(64) contour_mask_kernel(
    const float* __restrict__ contour,   // [NCONT, KV, 2]
    float* __restrict__ out)             // [NCONT, MSIZE, MSIZE]
{
    __shared__ float sx[KV];
    __shared__ float sy[KV];

    const int tile0 = blockIdx.x * 2;        // 128-px tiles, 512 per contour
    const int c = tile0 >> 9;
    const int t = threadIdx.x;

    {
        const float2 v = ((const float2*)contour)[c * KV + t];
        sx[t] = v.x;
        sy[t] = v.y;
    }
    __syncthreads();

    const ull C0 = pk(AT_C0, AT_C0), C1 = pk(AT_C1, AT_C1), C2 = pk(AT_C2, AT_C2);
    const ull C3 = pk(AT_C3, AT_C3), C4 = pk(AT_C4, AT_C4), C5 = pk(AT_C5, AT_C5);

#pragma unroll 1
    for (int tt = 0; tt < 2; tt++) {
        const int tile = tile0 + tt;
        const int pix  = ((tile & 511) << 7) + t * 2;     // within-contour pixel
        const float x  = (float)(pix >> 8)  * (1.0f / MSIZE);
        const float y0 = (float)(pix & 255) * (1.0f / MSIZE);
        const float y1 = y0 + (1.0f / MSIZE);

        float dx  = sx[0] - x;
        float dy0 = sy[0] - y0;
        float dy1 = sy[0] - y1;

        float S1a = 0.0f, Sta = 0.0f;    // pixel 0: sum t*cs, sum t
        float S1b = 0.0f, Stb = 0.0f;    // pixel 1

#pragma unroll 8
        for (int k = 0; k < KV; k++) {
            const int kn = (k + 1) & (KV - 1);
            const float rx  = sx[kn] - x;
            const float ry0 = sy[kn] - y0;
            const float ry1 = sy[kn] - y1;

            const float drs  = dx * rx;
            const float dot0 = fmaf(dy0, ry0, drs);
            const float dot1 = fmaf(dy1, ry1, drs);
            const float cr0  = fmaf(dy0, rx, -(dx * ry0));
            const float cr1  = fmaf(dy1, rx, -(dx * ry1));

            const float t0 = ftanh(KCONST * cr0);
            const float t1 = ftanh(KCONST * cr1);

            const float A0f = fabsf(cr0), D0 = fabsf(dot0);
            const float A1f = fabsf(cr1), D1 = fabsf(dot1);
            const float mn0 = fminf(A0f, D0), mx0 = fmaxf(A0f, D0);
            const float mn1 = fminf(A1f, D1), mx1 = fmaxf(A1f, D1);
            const float a0 = mn0 * frcp(mx0);
            const float a1 = mn1 * frcp(mx1);

            // packed atan poly: at = a * poly(a*a)
            const ull ap = pk(a0, a1);
            const ull s2 = f2mul(ap, ap);
            ull p = f2fma(s2, C5, C4);
            p = f2fma(p, s2, C3);
            p = f2fma(p, s2, C2);
            p = f2fma(p, s2, C1);
            p = f2fma(p, s2, C0);
            const ull atp = f2mul(p, ap);
            float at0, at1;
            upk(at0, at1, atp);

            // u = (|cr|>|dot|) ? at : pi/2-at  ==  |bsel - at|, bsel in {0, pi/2}
            const float b0 = (A0f > D0) ? 0.0f : HPI;
            const float b1 = (A1f > D1) ? 0.0f : HPI;
            const float u0 = fminf(fabsf(b0 - at0), UMAX);
            const float u1 = fminf(fabsf(b1 - at1), UMAX);

            // cs = copysign(u, dot);  angle = pi/2 - cs
            const float cs0 = __int_as_float(__float_as_int(u0) |
                                             (__float_as_int(dot0) & 0x80000000u));
            const float cs1 = __int_as_float(__float_as_int(u1) |
                                             (__float_as_int(dot1) & 0x80000000u));

            S1a = fmaf(t0, cs0, S1a);  Sta += t0;
            S1b = fmaf(t1, cs1, S1b);  Stb += t1;

            dx = rx; dy0 = ry0; dy1 = ry1;
        }

        float2 o;
        o.x = fminf(fabsf(fmaf(HPI, Sta, -S1a)) * INV2PI, 1.0f);
        o.y = fminf(fabsf(fmaf(HPI, Stb, -S1b)) * INV2PI, 1.0f);
        ((float2*)out)[(c * (MSIZE * MSIZE) + pix) >> 1] = o;
    }
}

extern "C" void kernel_launch(void* const* d_in, const int* in_sizes, int n_in,
                              void* d_out, int out_size)
{
    const float* contour = (const float*)d_in[0];
    float* out = (float*)d_out;

    contour_mask_kernel<<<2048, 64>>>(contour, out);
}

// round 5
// speedup vs baseline: 1.0617x; 1.0069x over previous
#include <cuda_runtime.h>

// Contour_to_mask via winding angles.
// angle_k = acos(clip(dot/(|d||r|), ±(1-1e-5))) == clamp(atan2(|cr|,dot), A0, pi-A0)
// sign_k = tanh(K*cr);  out = min(|sum_k sign_k*angle_k|/2pi, 1)
//
// All coords prescaled by sqrt(K): dot'=K*dot, cr'=K*cr -> atan ratio unchanged,
// tanh arg is cr' directly (no K multiply in the loop).
// 256-thread blocks, 2 pixels/thread, forced 7 blocks/SM (single wave).

#define MSIZE   256
#define KV      64
#define NCONT   8

#define SQRTK     316.2277660168379f
#define XSCALE    1.2352647109f        /* SQRTK / 256 */

// atan minimax on [0,1]: atan(a) ~= a*(c0 + c1 s + ... + c5 s^5), s=a*a
#define AT_C0  0.99997726f
#define AT_C1 -0.33262347f
#define AT_C2  0.19354346f
#define AT_C3 -0.11643287f
#define AT_C4  0.05265332f
#define AT_C5 -0.01172120f

#define HPI     1.5707963267948966f
#define UMAX    1.5663241850f          /* pi/2 - acos(1-1e-5) */
#define INV2PI  0.15915494309189535f

__device__ __forceinline__ float frcp(float x) {
    float r; asm("rcp.approx.f32 %0,%1;" : "=f"(r) : "f"(x)); return r;
}
__device__ __forceinline__ float ftanh(float x) {
    float r; asm("tanh.approx.f32 %0,%1;" : "=f"(r) : "f"(x)); return r;
}

__global__ void __launch_bounds__(256, 7) contour_mask_kernel(
    const float* __restrict__ contour,   // [NCONT, KV, 2]
    float* __restrict__ out)             // [NCONT, MSIZE, MSIZE]
{
    __shared__ float2 sv[KV];   // prescaled (X, Y) per vertex

    const int c = blockIdx.y;
    const int t = threadIdx.x;

    if (t < KV) {
        const float2 v = ((const float2*)contour)[c * KV + t];
        sv[t] = make_float2(v.x * SQRTK, v.y * SQRTK);
    }
    __syncthreads();

    const int gid  = blockIdx.x * blockDim.x + t;     // 0 .. 32767
    const int pix0 = gid * 2;
    const float xs  = (float)(pix0 >> 8)  * XSCALE;
    const float ys0 = (float)(pix0 & 255) * XSCALE;
    const float ys1 = ys0 + XSCALE;

    float2 v0 = sv[0];
    float dx  = v0.x - xs;
    float dy0 = v0.y - ys0;
    float dy1 = v0.y - ys1;

    float S1a = 0.0f, Sta = 0.0f;    // pixel 0: sum t*cs, sum t
    float S1b = 0.0f, Stb = 0.0f;    // pixel 1

#pragma unroll 8
    for (int k = 0; k < KV; k++) {
        const int kn = (k + 1) & (KV - 1);
        const float2 vn = sv[kn];
        const float rx  = vn.x - xs;
        const float ry0 = vn.y - ys0;
        const float ry1 = vn.y - ys1;

        const float drs  = dx * rx;
        const float dot0 = fmaf(dy0, ry0, drs);
        const float dot1 = fmaf(dy1, ry1, drs);
        const float cr0  = fmaf(dy0, rx, -(dx * ry0));   // K-scaled cross
        const float cr1  = fmaf(dy1, rx, -(dx * ry1));

        const float t0 = ftanh(cr0);                      // == tanh(K*cross)
        const float t1 = ftanh(cr1);

        const float A0f = fabsf(cr0), D0 = fabsf(dot0);
        const float A1f = fabsf(cr1), D1 = fabsf(dot1);
        const float mn0 = fminf(A0f, D0), mx0 = fmaxf(A0f, D0);
        const float mn1 = fminf(A1f, D1), mx1 = fmaxf(A1f, D1);
        const float a0 = mn0 * frcp(mx0);
        const float a1 = mn1 * frcp(mx1);

        // scalar atan poly, immediate constants (FFMA-imm, rt 1, zero const regs)
        const float s0 = a0 * a0;
        const float s1 = a1 * a1;
        float p0 = fmaf(s0, AT_C5, AT_C4);
        float p1 = fmaf(s1, AT_C5, AT_C4);
        p0 = fmaf(p0, s0, AT_C3);  p1 = fmaf(p1, s1, AT_C3);
        p0 = fmaf(p0, s0, AT_C2);  p1 = fmaf(p1, s1, AT_C2);
        p0 = fmaf(p0, s0, AT_C1);  p1 = fmaf(p1, s1, AT_C1);
        p0 = fmaf(p0, s0, AT_C0);  p1 = fmaf(p1, s1, AT_C0);
        const float at0 = p0 * a0;
        const float at1 = p1 * a1;

        // u = (|cr|>|dot|) ? at : pi/2-at  ==  |bsel - at|, bsel in {0, pi/2}
        const float b0 = (A0f > D0) ? 0.0f : HPI;
        const float b1 = (A1f > D1) ? 0.0f : HPI;
        const float u0 = fminf(fabsf(b0 - at0), UMAX);
        const float u1 = fminf(fabsf(b1 - at1), UMAX);

        // cs = copysign(u, dot);  angle = pi/2 - cs
        const float cs0 = __int_as_float(__float_as_int(u0) |
                                         (__float_as_int(dot0) & 0x80000000u));
        const float cs1 = __int_as_float(__float_as_int(u1) |
                                         (__float_as_int(dot1) & 0x80000000u));

        S1a = fmaf(t0, cs0, S1a);  Sta += t0;
        S1b = fmaf(t1, cs1, S1b);  Stb += t1;

        dx = rx; dy0 = ry0; dy1 = ry1;
    }

    float2 o;
    o.x = fminf(fabsf(fmaf(HPI, Sta, -S1a)) * INV2PI, 1.0f);
    o.y = fminf(fabsf(fmaf(HPI, Stb, -S1b)) * INV2PI, 1.0f);
    ((float2*)out)[c * (MSIZE * MSIZE / 2) + gid] = o;
}

extern "C" void kernel_launch(void* const* d_in, const int* in_sizes, int n_in,
                              void* d_out, int out_size)
{
    const float* contour = (const float*)d_in[0];
    float* out = (float*)d_out;

    dim3 grid((MSIZE * MSIZE) / (2 * 256), NCONT);   // 128 x 8 = 1024 blocks
    contour_mask_kernel<<<grid, 256>>>(contour, out);
}

// round 6
// speedup vs baseline: 1.1152x; 1.0504x over previous
#include <cuda_runtime.h>

// Contour_to_mask via winding angles.
// angle_k = acos(clip(dot/(|d||r|), ±(1-1e-5))) == clamp(atan2(|cr|,dot), A0, pi-A0)
// sign_k = tanh(K*cr);  out = min(|sum_k sign_k*angle_k|/2pi, 1)
//
// Coords prescaled by sqrt(K): tanh arg = scaled cross directly; atan ratio invariant.
// 2 px/thread; y-dependent math + atan poly packed f32x2; forced 7 blocks/SM.

#define MSIZE   256
#define KV      64
#define NCONT   8

#define SQRTK   316.2277660168379f
#define XSC     1.2352647109f          /* SQRTK / 256 */

typedef unsigned long long ull;

__device__ __forceinline__ ull pk(float lo, float hi) {
    ull r; asm("mov.b64 %0, {%1,%2};" : "=l"(r) : "f"(lo), "f"(hi)); return r;
}
__device__ __forceinline__ void upk(float& lo, float& hi, ull v) {
    asm("mov.b64 {%0,%1}, %2;" : "=f"(lo), "=f"(hi) : "l"(v));
}
__device__ __forceinline__ ull f2add(ull a, ull b) {
    ull d; asm("add.rn.f32x2 %0,%1,%2;" : "=l"(d) : "l"(a), "l"(b)); return d;
}
__device__ __forceinline__ ull f2mul(ull a, ull b) {
    ull d; asm("mul.rn.f32x2 %0,%1,%2;" : "=l"(d) : "l"(a), "l"(b)); return d;
}
__device__ __forceinline__ ull f2fma(ull a, ull b, ull c) {
    ull d; asm("fma.rn.f32x2 %0,%1,%2,%3;" : "=l"(d) : "l"(a), "l"(b), "l"(c)); return d;
}
__device__ __forceinline__ float frcp(float x) {
    float r; asm("rcp.approx.f32 %0,%1;" : "=f"(r) : "f"(x)); return r;
}
__device__ __forceinline__ float ftanh(float x) {
    float r; asm("tanh.approx.f32 %0,%1;" : "=f"(r) : "f"(x)); return r;
}

// atan deg-9 minimax on [0,1]: atan(a) ~= a*(p0 + p1 s + p2 s^2 + p3 s^3 + p4 s^4)
#define AP0  0.9998660f
#define AP1 -0.3302995f
#define AP2  0.1801410f
#define AP3 -0.0851330f
#define AP4  0.0208351f

#define HPI     1.5707963267948966f
#define UMAX    1.5663241850f          /* pi/2 - acos(1-1e-5) */
#define INV2PI  0.15915494309189535f

__global__ void __launch_bounds__(256, 7) contour_mask_kernel(
    const float* __restrict__ contour,   // [NCONT, KV, 2]
    float* __restrict__ out)             // [NCONT, MSIZE, MSIZE]
{
    __shared__ float sx[KV];
    __shared__ ull   sy2[KV];   // prescaled (cy, cy) pairs

    const int c = blockIdx.y;
    const int t = threadIdx.x;

    if (t < KV) {
        const float2 v = ((const float2*)contour)[c * KV + t];
        sx[t] = v.x * SQRTK;
        const float ys = v.y * SQRTK;
        sy2[t] = pk(ys, ys);
    }
    __syncthreads();

    const int gid  = blockIdx.x * blockDim.x + t;     // 0 .. 32767
    const int pix0 = gid * 2;
    const float xs = (float)(pix0 >> 8)  * XSC;
    const float y0 = (float)(pix0 & 255) * XSC;
    const ull negyp = pk(-y0, -(y0 + XSC));

    const ull P0 = pk(AP0, AP0), P1 = pk(AP1, AP1), P2 = pk(AP2, AP2);
    const ull P3 = pk(AP3, AP3), P4 = pk(AP4, AP4);

    float dx  = sx[0] - xs;
    ull   dyp = f2add(sy2[0], negyp);
    ull   NDX2 = pk(xs - sx[0], xs - sx[0]);

    float S1a = 0.0f, Sta = 0.0f;    // pixel 0: sum t*cs, sum t
    float S1b = 0.0f, Stb = 0.0f;    // pixel 1

#pragma unroll 4
    for (int k = 0; k < KV; k++) {
        const int kn = (k + 1) & (KV - 1);
        const float vx = sx[kn];
        const ull  ryp = f2add(sy2[kn], negyp);
        const float rx  = vx - xs;
        const float nrx = xs - vx;

        const float drs = dx * rx;
        const ull dotp = f2fma(dyp, ryp, pk(drs, drs));              // K*dot
        const ull crp  = f2fma(dyp, pk(rx, rx), f2mul(NDX2, ryp));   // K*cross

        float cr0, cr1, d0, d1;
        upk(cr0, cr1, crp); upk(d0, d1, dotp);

        const float t0 = ftanh(cr0);        // == tanh(K*cross)
        const float t1 = ftanh(cr1);

        const float A0f = fabsf(cr0), D0 = fabsf(d0);
        const float A1f = fabsf(cr1), D1 = fabsf(d1);
        const float mn0 = fminf(A0f, D0), mx0 = fmaxf(A0f, D0);
        const float mn1 = fminf(A1f, D1), mx1 = fmaxf(A1f, D1);
        const float a0 = mn0 * frcp(mx0);
        const float a1 = mn1 * frcp(mx1);

        // packed atan poly: at = a * poly(a*a)
        const ull ap = pk(a0, a1);
        const ull s2 = f2mul(ap, ap);
        ull p = f2fma(s2, P4, P3);
        p = f2fma(p, s2, P2);
        p = f2fma(p, s2, P1);
        p = f2fma(p, s2, P0);
        const ull atp = f2mul(p, ap);
        float at0, at1;
        upk(at0, at1, atp);

        // u = (|cr|>|dot|) ? at : pi/2-at  ==  |bsel - at|, bsel in {0, pi/2}
        const float b0 = (A0f > D0) ? 0.0f : HPI;
        const float b1 = (A1f > D1) ? 0.0f : HPI;
        const float u0 = fminf(fabsf(b0 - at0), UMAX);
        const float u1 = fminf(fabsf(b1 - at1), UMAX);

        // cs = copysign(u, dot);  angle = pi/2 - cs
        const float cs0 = __int_as_float(__float_as_int(u0) |
                                         (__float_as_int(d0) & 0x80000000u));
        const float cs1 = __int_as_float(__float_as_int(u1) |
                                         (__float_as_int(d1) & 0x80000000u));

        S1a = fmaf(t0, cs0, S1a);  Sta += t0;
        S1b = fmaf(t1, cs1, S1b);  Stb += t1;

        dx = rx; dyp = ryp; NDX2 = pk(nrx, nrx);
    }

    float2 o;
    o.x = fminf(fabsf(fmaf(HPI, Sta, -S1a)) * INV2PI, 1.0f);
    o.y = fminf(fabsf(fmaf(HPI, Stb, -S1b)) * INV2PI, 1.0f);
    ((float2*)out)[c * (MSIZE * MSIZE / 2) + gid] = o;
}

extern "C" void kernel_launch(void* const* d_in, const int* in_sizes, int n_in,
                              void* d_out, int out_size)
{
    const float* contour = (const float*)d_in[0];
    float* out = (float*)d_out;

    dim3 grid((MSIZE * MSIZE) / (2 * 256), NCONT);   // 128 x 8 = 1024 blocks
    contour_mask_kernel<<<grid, 256>>>(contour, out);
}

// round 7
// speedup vs baseline: 1.1233x; 1.0073x over previous
#include <cuda_runtime.h>

// Contour_to_mask via winding angles.
// angle_k = acos(clip(dot/(|d||r|), ±(1-1e-5))) == clamp(atan2(|cr|,dot), A0, pi-A0)
// sign_k = tanh(K*cr);  out = min(|sum_k sign_k*angle_k|/2pi, 1)
//
// Coords prescaled by sqrt(K); 2 px/thread; geometry + atan poly packed f32x2;
// vertices in smem as (X,X,Y,Y) float4 -> single LDS.128 per iteration.

#define MSIZE   256
#define KV      64
#define NCONT   8

#define SQRTK   316.2277660168379f
#define XSC     1.2352647109f          /* SQRTK / 256 */

typedef unsigned long long ull;

__device__ __forceinline__ ull pk(float lo, float hi) {
    ull r; asm("mov.b64 %0, {%1,%2};" : "=l"(r) : "f"(lo), "f"(hi)); return r;
}
__device__ __forceinline__ void upk(float& lo, float& hi, ull v) {
    asm("mov.b64 {%0,%1}, %2;" : "=f"(lo), "=f"(hi) : "l"(v));
}
__device__ __forceinline__ ull f2add(ull a, ull b) {
    ull d; asm("add.rn.f32x2 %0,%1,%2;" : "=l"(d) : "l"(a), "l"(b)); return d;
}
__device__ __forceinline__ ull f2mul(ull a, ull b) {
    ull d; asm("mul.rn.f32x2 %0,%1,%2;" : "=l"(d) : "l"(a), "l"(b)); return d;
}
__device__ __forceinline__ ull f2fma(ull a, ull b, ull c) {
    ull d; asm("fma.rn.f32x2 %0,%1,%2,%3;" : "=l"(d) : "l"(a), "l"(b), "l"(c)); return d;
}
__device__ __forceinline__ float frcp(float x) {
    float r; asm("rcp.approx.f32 %0,%1;" : "=f"(r) : "f"(x)); return r;
}
__device__ __forceinline__ float ftanh(float x) {
    float r; asm("tanh.approx.f32 %0,%1;" : "=f"(r) : "f"(x)); return r;
}

// atan deg-9 minimax on [0,1]: atan(a) ~= a*(p0 + p1 s + p2 s^2 + p3 s^3 + p4 s^4)
#define AP0  0.9998660f
#define AP1 -0.3302995f
#define AP2  0.1801410f
#define AP3 -0.0851330f
#define AP4  0.0208351f

#define HPI     1.5707963267948966f
#define UMAX    1.5663241850f          /* pi/2 - acos(1-1e-5) */
#define INV2PI  0.15915494309189535f

__global__ void __launch_bounds__(256, 8) contour_mask_kernel(
    const float* __restrict__ contour,   // [NCONT, KV, 2]
    float* __restrict__ out)             // [NCONT, MSIZE, MSIZE]
{
    __shared__ float4 sv[KV];   // prescaled (X, X, Y, Y)

    const int c = blockIdx.y;
    const int t = threadIdx.x;

    if (t < KV) {
        const float2 v = ((const float2*)contour)[c * KV + t];
        const float X = v.x * SQRTK;
        const float Y = v.y * SQRTK;
        sv[t] = make_float4(X, X, Y, Y);
    }
    __syncthreads();

    const int gid  = blockIdx.x * blockDim.x + t;     // 0 .. 32767
    const int pix0 = gid * 2;
    const float xs = (float)(pix0 >> 8)  * XSC;
    const float y0 = (float)(pix0 & 255) * XSC;
    const ull negyp = pk(-y0, -(y0 + XSC));

    const ull P0 = pk(AP0, AP0), P1 = pk(AP1, AP1), P2 = pk(AP2, AP2);
    const ull P3 = pk(AP3, AP3), P4 = pk(AP4, AP4);
    const ull MNEG1 = pk(-1.0f, -1.0f);

    // k = 0 state
    float4 q0 = sv[0];
    ull DX2  = pk(q0.x - xs, q0.x - xs);
    ull NDX2 = f2mul(DX2, MNEG1);
    ull dyp  = f2add(pk(q0.z, q0.w), negyp);

    float S1a = 0.0f, Sta = 0.0f;    // pixel 0: sum t*cs, sum t
    float S1b = 0.0f, Stb = 0.0f;    // pixel 1

#pragma unroll 4
    for (int k = 0; k < KV; k++) {
        const int kn = (k + 1) & (KV - 1);
        const float4 q = sv[kn];                 // LDS.128
        const float rx = q.x - xs;
        const ull RX2  = pk(rx, rx);
        const ull NRX2 = f2mul(RX2, MNEG1);
        const ull ryp  = f2add(pk(q.z, q.w), negyp);

        const ull dotp = f2fma(DX2, RX2, f2mul(dyp, ryp));   // K*dot
        const ull crp  = f2fma(dyp, RX2, f2mul(NDX2, ryp));  // K*cross

        float cr0, cr1, d0, d1;
        upk(cr0, cr1, crp); upk(d0, d1, dotp);

        const float t0 = ftanh(cr0);             // == tanh(K*cross)
        const float t1 = ftanh(cr1);

        const float A0f = fabsf(cr0), D0 = fabsf(d0);
        const float A1f = fabsf(cr1), D1 = fabsf(d1);
        const float mn0 = fminf(A0f, D0), mx0 = fmaxf(A0f, D0);
        const float mn1 = fminf(A1f, D1), mx1 = fmaxf(A1f, D1);
        const float a0 = mn0 * frcp(mx0);
        const float a1 = mn1 * frcp(mx1);

        // packed atan poly: at = a * poly(a*a)
        const ull ap = pk(a0, a1);
        const ull s2 = f2mul(ap, ap);
        ull p = f2fma(s2, P4, P3);
        p = f2fma(p, s2, P2);
        p = f2fma(p, s2, P1);
        p = f2fma(p, s2, P0);
        const ull atp = f2mul(p, ap);
        float at0, at1;
        upk(at0, at1, atp);

        // u = (|cr|>|dot|) ? at : pi/2-at  ==  |bsel - at|, bsel in {0, pi/2}
        const float b0 = (A0f > D0) ? 0.0f : HPI;
        const float b1 = (A1f > D1) ? 0.0f : HPI;
        const float u0 = fminf(fabsf(b0 - at0), UMAX);
        const float u1 = fminf(fabsf(b1 - at1), UMAX);

        // cs = copysign(u, dot);  angle = pi/2 - cs
        const float cs0 = __int_as_float(__float_as_int(u0) |
                                         (__float_as_int(d0) & 0x80000000u));
        const float cs1 = __int_as_float(__float_as_int(u1) |
                                         (__float_as_int(d1) & 0x80000000u));

        S1a = fmaf(t0, cs0, S1a);  Sta += t0;
        S1b = fmaf(t1, cs1, S1b);  Stb += t1;

        // rotate (register renames only)
        DX2 = RX2; NDX2 = NRX2; dyp = ryp;
    }

    float2 o;
    o.x = fminf(fabsf(fmaf(HPI, Sta, -S1a)) * INV2PI, 1.0f);
    o.y = fminf(fabsf(fmaf(HPI, Stb, -S1b)) * INV2PI, 1.0f);
    ((float2*)out)[c * (MSIZE * MSIZE / 2) + gid] = o;
}

extern "C" void kernel_launch(void* const* d_in, const int* in_sizes, int n_in,
                              void* d_out, int out_size)
{
    const float* contour = (const float*)d_in[0];
    float* out = (float*)d_out;

    dim3 grid((MSIZE * MSIZE) / (2 * 256), NCONT);   // 128 x 8 = 1024 blocks
    contour_mask_kernel<<<grid, 256>>>(contour, out);
}